// round 10
// baseline (speedup 1.0000x reference)
#include <cuda_runtime.h>
#include <stdint.h>

// ---------------------------------------------------------------------------
// HarmonicFullyConnectedTensorProduct (lmax=2, MUL=64, BATCH=1024, 11 paths)
// v5: 4 CTAs/SM (ZT=8, 42KB smem, <=128 regs), Phase A split into 4 path
//     groups with per-group operand loads, W via cp.async (unchanged).
// ---------------------------------------------------------------------------

typedef unsigned long long ull;

#define NP 11
__host__ __device__ constexpr int PL1[NP]  = {0,0,0,1,1,1,1,2,2,2,2};
__host__ __device__ constexpr int PL2[NP]  = {0,1,2,0,1,1,2,0,1,2,2};
__host__ __device__ constexpr int PL3[NP]  = {0,1,2,1,0,2,1,2,1,0,2};
__host__ __device__ constexpr int XOFF[3]  = {0,1,4};
// t-record per-path blocks padded even (stride 46)
__host__ __device__ constexpr int TOP[NP]  = {0,2,6,12,16,18,24,28,34,38,40};
// padded C layout: per (m,n) slot = m3+(m3&1) ulls; path bases (ull units)
__host__ __device__ constexpr int CPB[NP]  = {0,2,14,44,56,74,128,188,218,278,328};
#define C_TOT 478

#define ZT 8          // z rows per CTA (4 z-pairs)
#define ZP 4          // z-pairs per CTA
#define UT 8
#define VT 8
#define NVC 8
#define TREC 46
#define XSTR 10

// smem layout (ull units)
#define X1_OFF 0                    // 32 rec * 10 = 320
#define X2_OFF 320                  // 32 rec * 10 = 320
#define C_OFF  640                  // 480 (478 used)
#define T_OFF  1120                 // 32 rec * 46 = 1472
#define W_OFF  2592                 // 2816 ull = 5632 floats
#define SMEM_ULL  5408
#define SMEM_BYTES (SMEM_ULL*8)     // 43264 -> 4 CTAs/SM

// W transposed: [u][v][p][w] floats
__device__ float g_Wt[64 * 64 * NP * 64];

// ---------------- packed f32x2 helpers ----------------
__device__ __forceinline__ ull pk(float lo, float hi) {
    ull r;
    asm("mov.b64 %0, {%1, %2};" : "=l"(r) : "r"(__float_as_uint(lo)), "r"(__float_as_uint(hi)));
    return r;
}
__device__ __forceinline__ void unpk(ull v, float& lo, float& hi) {
    unsigned a, b;
    asm("mov.b64 {%0, %1}, %2;" : "=r"(a), "=r"(b) : "l"(v));
    lo = __uint_as_float(a); hi = __uint_as_float(b);
}
__device__ __forceinline__ ull fma2(ull a, ull b, ull c) {
    ull d;
    asm("fma.rn.f32x2 %0, %1, %2, %3;" : "=l"(d) : "l"(a), "l"(b), "l"(c));
    return d;
}
__device__ __forceinline__ ull mul2(ull a, ull b) {
    ull d;
    asm("mul.rn.f32x2 %0, %1, %2;" : "=l"(d) : "l"(a), "l"(b));
    return d;
}
__device__ __forceinline__ uint32_t s2u32(const void* p) {
    uint32_t a;
    asm("{ .reg .u64 t; cvta.to.shared.u64 t, %1; cvt.u32.u64 %0, t; }" : "=r"(a) : "l"(p));
    return a;
}
__device__ __forceinline__ void cpasync16(uint32_t dst, const void* src) {
    asm volatile("cp.async.cg.shared.global [%0], [%1], 16;" :: "r"(dst), "l"(src));
}
__device__ __forceinline__ void cpcommit() {
    asm volatile("cp.async.commit_group;");
}
__device__ __forceinline__ void cpwait0() {
    asm volatile("cp.async.wait_group 0;" ::: "memory");
}

// ---------------- W transpose ----------------
__global__ void transpose_W_kernel(const float* __restrict__ W) {
    int idx = blockIdx.x * 256 + threadIdx.x;   // g_Wt index, w fastest
    int w  = idx & 63;
    int p  = (idx >> 6) % NP;
    int uv = idx / (NP * 64);
    g_Wt[idx] = W[(((p << 6) + w) << 12) + uv];
}

// ---------------- Phase A: single path ----------------
template <int P>
__device__ __forceinline__ void pathA(const ull* a, const ull* b,
                                      const ull* __restrict__ c2, ull* trec) {
    constexpr int L1 = PL1[P], L2 = PL2[P], L3 = PL3[P];
    constexpr int M1 = 2*L1+1, M2 = 2*L2+1, M3 = 2*L3+1;
    constexpr int O1 = XOFF[L1], O2 = XOFF[L2];
    constexpr int CB = CPB[P], SLOT = M3 + (M3 & 1), TO = TOP[P];
    ull t[M3];
#pragma unroll
    for (int k = 0; k < M3; k++) t[k] = 0ull;
#pragma unroll
    for (int m = 0; m < M1; m++) {
        ull am = a[O1 + m];
#pragma unroll
        for (int n = 0; n < M2; n++) {
            ull o = mul2(am, b[O2 + n]);
            const int base = CB + (m*M2 + n)*SLOT;
#pragma unroll
            for (int kk = 0; kk < M3/2; kk++) {
                ulonglong2 q = *(const ulonglong2*)(c2 + base + 2*kk);
                t[2*kk]   = fma2(o, q.x, t[2*kk]);
                t[2*kk+1] = fma2(o, q.y, t[2*kk+1]);
            }
            if (M3 & 1)
                t[M3-1] = fma2(o, c2[base + M3 - 1], t[M3-1]);
        }
    }
#pragma unroll
    for (int kk = 0; kk < M3/2; kk++) {
        ulonglong2 s; s.x = t[2*kk]; s.y = t[2*kk+1];
        *(ulonglong2*)(trec + TO + 2*kk) = s;
    }
    if (M3 & 1) {
        ulonglong2 s; s.x = t[M3-1]; s.y = t[M3-1];
        *(ulonglong2*)(trec + TO + M3 - 1) = s;
    }
}

// operand pair load from smem record
#define LDP(dst, src, i) { ulonglong2 _q = *(const ulonglong2*)((src) + (i)); \
                           (dst)[i] = _q.x; (dst)[(i)+1] = _q.y; }

// ---------------- Phase B: one path, 4 w per thread (W from smem) ----------------
template <int P>
__device__ __forceinline__ void pathB(const float* __restrict__ wv,
                                      const ull* __restrict__ tp,
                                      ull (&acc)[4][9]) {
    constexpr int M3 = 2*PL3[P]+1, TO = TOP[P], KO = XOFF[PL3[P]];
    float4 wf = *(const float4*)(wv + P * 64);
    ull w0 = pk(wf.x, wf.x);
    ull w1 = pk(wf.y, wf.y);
    ull w2 = pk(wf.z, wf.z);
    ull w3 = pk(wf.w, wf.w);
    const ulonglong2* tc = (const ulonglong2*)(tp + TO);
    ulonglong2 q[(M3 + 1) / 2];
#pragma unroll
    for (int i = 0; i < (M3 + 1) / 2; i++) q[i] = tc[i];
#pragma unroll
    for (int k = 0; k < M3; k++) {
        ull tv = (k & 1) ? q[k >> 1].y : q[k >> 1].x;
        acc[0][KO+k] = fma2(w0, tv, acc[0][KO+k]);
        acc[1][KO+k] = fma2(w1, tv, acc[1][KO+k]);
        acc[2][KO+k] = fma2(w2, tv, acc[2][KO+k]);
        acc[3][KO+k] = fma2(w3, tv, acc[3][KO+k]);
    }
}

// ---------------- main fused kernel ----------------
__global__ void __launch_bounds__(128, 4)
tp_kernel(const float* __restrict__ x1_0, const float* __restrict__ x2_0,
          const float* __restrict__ x1_1, const float* __restrict__ x2_1,
          const float* __restrict__ x1_2, const float* __restrict__ x2_2,
          const float* __restrict__ C0,  const float* __restrict__ C1,
          const float* __restrict__ C2,  const float* __restrict__ C3,
          const float* __restrict__ C4,  const float* __restrict__ C5,
          const float* __restrict__ C6,  const float* __restrict__ C7,
          const float* __restrict__ C8,  const float* __restrict__ C9,
          const float* __restrict__ C10,
          float* __restrict__ out) {
    extern __shared__ ull sm[];
    ull* x1s = sm + X1_OFF;
    ull* x2s = sm + X2_OFF;
    ull* c2s = sm + C_OFF;
    ull* t2s = sm + T_OFF;
    const float* wsm = (const float*)(sm + W_OFF);
    const uint32_t wdst0 = s2u32(sm + W_OFF);

    const int tid   = threadIdx.x;
    const int zbase = blockIdx.x * ZT;
    const int ubase = blockIdx.y * UT;

    // ---- stage C (padded slots, dup into both f32x2 lanes) ----
    {
        const float* cps[NP] = {C0,C1,C2,C3,C4,C5,C6,C7,C8,C9,C10};
        for (int idx = tid; idx < C_TOT; idx += 128) {
            int p = 0;
#pragma unroll
            for (int q = 1; q < NP; q++) if (idx >= CPB[q]) p = q;
            int off  = idx - CPB[p];
            int m3   = 2*PL3[p] + 1;
            int slot = m3 + (m3 & 1);
            int mn   = off / slot;
            int k    = off % slot;
            float c  = (k < m3) ? cps[p][mn*m3 + k] : 0.0f;
            c2s[idx] = pk(c, c);
        }
    }
    // ---- stage x1s [ul*4+zp][10] ----
    for (int idx = tid; idx < UT*ZP*9; idx += 128) {
        int rec = idx / 9; int m = idx % 9;
        int ul = rec >> 2, zp = rec & 3;
        int u  = ubase + ul;
        int z0 = zbase + zp*2;
        float a, b;
        if (m == 0)      { a = x1_0[z0*64 + u];            b = x1_0[(z0+1)*64 + u]; }
        else if (m < 4)  { a = x1_1[(z0*64 + u)*3 + m-1];  b = x1_1[((z0+1)*64 + u)*3 + m-1]; }
        else             { a = x1_2[(z0*64 + u)*5 + m-4];  b = x1_2[((z0+1)*64 + u)*5 + m-4]; }
        x1s[rec*XSTR + m] = pk(a, b);
    }

    // thread identities
    // Phase A: rec = tid & 31 -> (zpA = rec&3, vlA = rec>>2), grp = tid>>5
    const int recA = tid & 31;
    const int grp  = tid >> 5;
    // Phase B: zp = tid&3, wo = (tid>>2)&15 (w = 4*wo..), vg = tid>>6 (v half)
    const int zp = tid & 3;
    const int wo = (tid >> 2) & 15;
    const int vg = tid >> 6;

    ull acc[4][9];
#pragma unroll
    for (int j = 0; j < 4; j++)
#pragma unroll
        for (int k = 0; k < 9; k++) acc[j][k] = 0ull;

    for (int vc = 0; vc < NVC; vc++) {
        // ---- stage x2s chunk [vl*4+zp][10] ----
        for (int idx = tid; idx < VT*ZP*9; idx += 128) {
            int rec = idx / 9; int n = idx % 9;
            int vl = rec >> 2, zpp = rec & 3;
            int v  = vc*VT + vl;
            int z0 = zbase + zpp*2;
            float a, b;
            if (n == 0)      { a = x2_0[z0*64 + v];            b = x2_0[(z0+1)*64 + v]; }
            else if (n < 4)  { a = x2_1[(z0*64 + v)*3 + n-1];  b = x2_1[((z0+1)*64 + v)*3 + n-1]; }
            else             { a = x2_2[(z0*64 + v)*5 + n-4];  b = x2_2[((z0+1)*64 + v)*5 + n-4]; }
            x2s[rec*XSTR + n] = pk(a, b);
        }
        __syncthreads();

        for (int ul = 0; ul < UT; ul++) {
            const int u = ubase + ul;
            // ---- kick off W tile copy (8v x 11p x 64w floats = 22.5KB) ----
            {
                const float* gsrc = g_Wt + (size_t)((u << 6) + vc*VT) * (NP*64);
#pragma unroll
                for (int i = 0; i < 11; i++) {
                    int c = tid + i*128;
                    cpasync16(wdst0 + c*16, gsrc + c*4);
                }
                cpcommit();
            }
            // -------- Phase A (4 path groups, per-group operand loads) --------
            {
                const ull* ap = x1s + (ul*ZP + (recA & 3))*XSTR;
                const ull* bp = x2s + recA*XSTR;
                ull* trec = t2s + recA*TREC;
                ull a[9], b[9];
                if (grp == 0) {
                    // p10 (2,2,2): a4-8, b4-8
                    LDP(a, ap, 4); LDP(a, ap, 6); a[8] = ap[8];
                    LDP(b, bp, 4); LDP(b, bp, 6); b[8] = bp[8];
                    pathA<10>(a, b, c2s, trec);
                } else if (grp == 1) {
                    // p5 (1,1,2): a1-3,b1-3 ; p8 (2,1,1): a4-8,b1-3
                    LDP(a, ap, 0); LDP(a, ap, 2); LDP(a, ap, 4); LDP(a, ap, 6); a[8] = ap[8];
                    LDP(b, bp, 0); LDP(b, bp, 2);
                    pathA<5>(a, b, c2s, trec);
                    pathA<8>(a, b, c2s, trec);
                } else if (grp == 2) {
                    // p6 (1,2,1), p2 (0,2,2), p4 (1,1,0), p3 (1,0,1): a0-3, b0-8
                    LDP(a, ap, 0); LDP(a, ap, 2);
                    LDP(b, bp, 0); LDP(b, bp, 2); LDP(b, bp, 4); LDP(b, bp, 6); b[8] = bp[8];
                    pathA<6>(a, b, c2s, trec);
                    pathA<2>(a, b, c2s, trec);
                    pathA<4>(a, b, c2s, trec);
                    pathA<3>(a, b, c2s, trec);
                } else {
                    // p7 (2,0,2), p9 (2,2,0), p1 (0,1,1), p0 (0,0,0): a0,a4-8, b0-8
                    a[0] = ap[0];
                    LDP(a, ap, 4); LDP(a, ap, 6); a[8] = ap[8];
                    LDP(b, bp, 0); LDP(b, bp, 2); LDP(b, bp, 4); LDP(b, bp, 6); b[8] = bp[8];
                    pathA<7>(a, b, c2s, trec);
                    pathA<9>(a, b, c2s, trec);
                    pathA<1>(a, b, c2s, trec);
                    pathA<0>(a, b, c2s, trec);
                }
            }
            cpwait0();
            __syncthreads();
            // -------- Phase B (vg half of v, 4 w, 1 z-pair per thread) --------
            {
                const float* wv = wsm + (vg*4) * (NP*64) + wo*4;
                const ull*   tp = t2s + ((vg*4)*ZP + zp)*TREC;
#pragma unroll 1
                for (int vi = 0; vi < 4; vi++) {
                    pathB<0>(wv, tp, acc);
                    pathB<1>(wv, tp, acc);
                    pathB<2>(wv, tp, acc);
                    pathB<3>(wv, tp, acc);
                    pathB<4>(wv, tp, acc);
                    pathB<5>(wv, tp, acc);
                    pathB<6>(wv, tp, acc);
                    pathB<7>(wv, tp, acc);
                    pathB<8>(wv, tp, acc);
                    pathB<9>(wv, tp, acc);
                    pathB<10>(wv, tp, acc);
                    wv += NP*64;        // next v in W tile
                    tp += ZP*TREC;      // next vl record
                }
            }
            __syncthreads();
        }
    }

    // ---- epilogue: combine u-splits & v-halves via atomics ----
    const int z0 = zbase + zp*2;
#pragma unroll
    for (int j = 0; j < 4; j++) {
        const int w = wo*4 + j;
#pragma unroll
        for (int k = 0; k < 9; k++) {
            float lo, hi;
            unpk(acc[j][k], lo, hi);
            atomicAdd(&out[(z0*64 + w)*9 + k], lo);
            atomicAdd(&out[((z0+1)*64 + w)*9 + k], hi);
        }
    }
}

// ---------------------------------------------------------------------------
extern "C" void kernel_launch(void* const* d_in, const int* in_sizes, int n_in,
                              void* d_out, int out_size) {
    const float* x1_0 = (const float*)d_in[0];
    const float* x2_0 = (const float*)d_in[1];
    const float* x1_1 = (const float*)d_in[2];
    const float* x2_1 = (const float*)d_in[3];
    const float* x1_2 = (const float*)d_in[4];
    const float* x2_2 = (const float*)d_in[5];
    const float* W    = (const float*)d_in[6];
    float* out = (float*)d_out;
    (void)in_sizes; (void)n_in;

    cudaFuncSetAttribute(tp_kernel, cudaFuncAttributeMaxDynamicSharedMemorySize, SMEM_BYTES);

    cudaMemsetAsync(d_out, 0, (size_t)out_size * sizeof(float), 0);

    int nW = 64 * 64 * NP * 64;
    transpose_W_kernel<<<nW / 256, 256>>>(W);

    dim3 grid(1024 / ZT, 64 / UT);   // (128, 8) = 1024 blocks
    tp_kernel<<<grid, 128, SMEM_BYTES>>>(
        x1_0, x2_0, x1_1, x2_1, x1_2, x2_2,
        (const float*)d_in[7],  (const float*)d_in[8],  (const float*)d_in[9],
        (const float*)d_in[10], (const float*)d_in[11], (const float*)d_in[12],
        (const float*)d_in[13], (const float*)d_in[14], (const float*)d_in[15],
        (const float*)d_in[16], (const float*)d_in[17],
        out);
}

// round 11
// speedup vs baseline: 1.0039x; 1.0039x over previous
#include <cuda_runtime.h>
#include <stdint.h>

// ---------------------------------------------------------------------------
// HarmonicFullyConnectedTensorProduct (lmax=2, MUL=64, BATCH=1024, 11 paths)
// v5: 4 CTAs/SM (ZT=8, 42KB smem, <=128 regs), Phase A split into 4 path
//     groups with per-group operand loads, W via cp.async (unchanged).
// ---------------------------------------------------------------------------

typedef unsigned long long ull;

#define NP 11
__host__ __device__ constexpr int PL1[NP]  = {0,0,0,1,1,1,1,2,2,2,2};
__host__ __device__ constexpr int PL2[NP]  = {0,1,2,0,1,1,2,0,1,2,2};
__host__ __device__ constexpr int PL3[NP]  = {0,1,2,1,0,2,1,2,1,0,2};
__host__ __device__ constexpr int XOFF[3]  = {0,1,4};
// t-record per-path blocks padded even (stride 46)
__host__ __device__ constexpr int TOP[NP]  = {0,2,6,12,16,18,24,28,34,38,40};
// padded C layout: per (m,n) slot = m3+(m3&1) ulls; path bases (ull units)
__host__ __device__ constexpr int CPB[NP]  = {0,2,14,44,56,74,128,188,218,278,328};
#define C_TOT 478

#define ZT 8          // z rows per CTA (4 z-pairs)
#define ZP 4          // z-pairs per CTA
#define UT 8
#define VT 8
#define NVC 8
#define TREC 46
#define XSTR 10

// smem layout (ull units)
#define X1_OFF 0                    // 32 rec * 10 = 320
#define X2_OFF 320                  // 32 rec * 10 = 320
#define C_OFF  640                  // 480 (478 used)
#define T_OFF  1120                 // 32 rec * 46 = 1472
#define W_OFF  2592                 // 2816 ull = 5632 floats
#define SMEM_ULL  5408
#define SMEM_BYTES (SMEM_ULL*8)     // 43264 -> 4 CTAs/SM

// W transposed: [u][v][p][w] floats
__device__ float g_Wt[64 * 64 * NP * 64];

// ---------------- packed f32x2 helpers ----------------
__device__ __forceinline__ ull pk(float lo, float hi) {
    ull r;
    asm("mov.b64 %0, {%1, %2};" : "=l"(r) : "r"(__float_as_uint(lo)), "r"(__float_as_uint(hi)));
    return r;
}
__device__ __forceinline__ void unpk(ull v, float& lo, float& hi) {
    unsigned a, b;
    asm("mov.b64 {%0, %1}, %2;" : "=r"(a), "=r"(b) : "l"(v));
    lo = __uint_as_float(a); hi = __uint_as_float(b);
}
__device__ __forceinline__ ull fma2(ull a, ull b, ull c) {
    ull d;
    asm("fma.rn.f32x2 %0, %1, %2, %3;" : "=l"(d) : "l"(a), "l"(b), "l"(c));
    return d;
}
__device__ __forceinline__ ull mul2(ull a, ull b) {
    ull d;
    asm("mul.rn.f32x2 %0, %1, %2;" : "=l"(d) : "l"(a), "l"(b));
    return d;
}
__device__ __forceinline__ uint32_t s2u32(const void* p) {
    uint32_t a;
    asm("{ .reg .u64 t; cvta.to.shared.u64 t, %1; cvt.u32.u64 %0, t; }" : "=r"(a) : "l"(p));
    return a;
}
__device__ __forceinline__ void cpasync16(uint32_t dst, const void* src) {
    asm volatile("cp.async.cg.shared.global [%0], [%1], 16;" :: "r"(dst), "l"(src));
}
__device__ __forceinline__ void cpcommit() {
    asm volatile("cp.async.commit_group;");
}
__device__ __forceinline__ void cpwait0() {
    asm volatile("cp.async.wait_group 0;" ::: "memory");
}

// ---------------- W transpose ----------------
__global__ void transpose_W_kernel(const float* __restrict__ W) {
    int idx = blockIdx.x * 256 + threadIdx.x;   // g_Wt index, w fastest
    int w  = idx & 63;
    int p  = (idx >> 6) % NP;
    int uv = idx / (NP * 64);
    g_Wt[idx] = W[(((p << 6) + w) << 12) + uv];
}

// ---------------- Phase A: single path ----------------
template <int P>
__device__ __forceinline__ void pathA(const ull* a, const ull* b,
                                      const ull* __restrict__ c2, ull* trec) {
    constexpr int L1 = PL1[P], L2 = PL2[P], L3 = PL3[P];
    constexpr int M1 = 2*L1+1, M2 = 2*L2+1, M3 = 2*L3+1;
    constexpr int O1 = XOFF[L1], O2 = XOFF[L2];
    constexpr int CB = CPB[P], SLOT = M3 + (M3 & 1), TO = TOP[P];
    ull t[M3];
#pragma unroll
    for (int k = 0; k < M3; k++) t[k] = 0ull;
#pragma unroll
    for (int m = 0; m < M1; m++) {
        ull am = a[O1 + m];
#pragma unroll
        for (int n = 0; n < M2; n++) {
            ull o = mul2(am, b[O2 + n]);
            const int base = CB + (m*M2 + n)*SLOT;
#pragma unroll
            for (int kk = 0; kk < M3/2; kk++) {
                ulonglong2 q = *(const ulonglong2*)(c2 + base + 2*kk);
                t[2*kk]   = fma2(o, q.x, t[2*kk]);
                t[2*kk+1] = fma2(o, q.y, t[2*kk+1]);
            }
            if (M3 & 1)
                t[M3-1] = fma2(o, c2[base + M3 - 1], t[M3-1]);
        }
    }
#pragma unroll
    for (int kk = 0; kk < M3/2; kk++) {
        ulonglong2 s; s.x = t[2*kk]; s.y = t[2*kk+1];
        *(ulonglong2*)(trec + TO + 2*kk) = s;
    }
    if (M3 & 1) {
        ulonglong2 s; s.x = t[M3-1]; s.y = t[M3-1];
        *(ulonglong2*)(trec + TO + M3 - 1) = s;
    }
}

// operand pair load from smem record
#define LDP(dst, src, i) { ulonglong2 _q = *(const ulonglong2*)((src) + (i)); \
                           (dst)[i] = _q.x; (dst)[(i)+1] = _q.y; }

// ---------------- Phase B: one path, 4 w per thread (W from smem) ----------------
template <int P>
__device__ __forceinline__ void pathB(const float* __restrict__ wv,
                                      const ull* __restrict__ tp,
                                      ull (&acc)[4][9]) {
    constexpr int M3 = 2*PL3[P]+1, TO = TOP[P], KO = XOFF[PL3[P]];
    float4 wf = *(const float4*)(wv + P * 64);
    ull w0 = pk(wf.x, wf.x);
    ull w1 = pk(wf.y, wf.y);
    ull w2 = pk(wf.z, wf.z);
    ull w3 = pk(wf.w, wf.w);
    const ulonglong2* tc = (const ulonglong2*)(tp + TO);
    ulonglong2 q[(M3 + 1) / 2];
#pragma unroll
    for (int i = 0; i < (M3 + 1) / 2; i++) q[i] = tc[i];
#pragma unroll
    for (int k = 0; k < M3; k++) {
        ull tv = (k & 1) ? q[k >> 1].y : q[k >> 1].x;
        acc[0][KO+k] = fma2(w0, tv, acc[0][KO+k]);
        acc[1][KO+k] = fma2(w1, tv, acc[1][KO+k]);
        acc[2][KO+k] = fma2(w2, tv, acc[2][KO+k]);
        acc[3][KO+k] = fma2(w3, tv, acc[3][KO+k]);
    }
}

// ---------------- main fused kernel ----------------
__global__ void __launch_bounds__(128, 4)
tp_kernel(const float* __restrict__ x1_0, const float* __restrict__ x2_0,
          const float* __restrict__ x1_1, const float* __restrict__ x2_1,
          const float* __restrict__ x1_2, const float* __restrict__ x2_2,
          const float* __restrict__ C0,  const float* __restrict__ C1,
          const float* __restrict__ C2,  const float* __restrict__ C3,
          const float* __restrict__ C4,  const float* __restrict__ C5,
          const float* __restrict__ C6,  const float* __restrict__ C7,
          const float* __restrict__ C8,  const float* __restrict__ C9,
          const float* __restrict__ C10,
          float* __restrict__ out) {
    extern __shared__ ull sm[];
    ull* x1s = sm + X1_OFF;
    ull* x2s = sm + X2_OFF;
    ull* c2s = sm + C_OFF;
    ull* t2s = sm + T_OFF;
    const float* wsm = (const float*)(sm + W_OFF);
    const uint32_t wdst0 = s2u32(sm + W_OFF);

    const int tid   = threadIdx.x;
    const int zbase = blockIdx.x * ZT;
    const int ubase = blockIdx.y * UT;

    // ---- stage C (padded slots, dup into both f32x2 lanes) ----
    {
        const float* cps[NP] = {C0,C1,C2,C3,C4,C5,C6,C7,C8,C9,C10};
        for (int idx = tid; idx < C_TOT; idx += 128) {
            int p = 0;
#pragma unroll
            for (int q = 1; q < NP; q++) if (idx >= CPB[q]) p = q;
            int off  = idx - CPB[p];
            int m3   = 2*PL3[p] + 1;
            int slot = m3 + (m3 & 1);
            int mn   = off / slot;
            int k    = off % slot;
            float c  = (k < m3) ? cps[p][mn*m3 + k] : 0.0f;
            c2s[idx] = pk(c, c);
        }
    }
    // ---- stage x1s [ul*4+zp][10] ----
    for (int idx = tid; idx < UT*ZP*9; idx += 128) {
        int rec = idx / 9; int m = idx % 9;
        int ul = rec >> 2, zp = rec & 3;
        int u  = ubase + ul;
        int z0 = zbase + zp*2;
        float a, b;
        if (m == 0)      { a = x1_0[z0*64 + u];            b = x1_0[(z0+1)*64 + u]; }
        else if (m < 4)  { a = x1_1[(z0*64 + u)*3 + m-1];  b = x1_1[((z0+1)*64 + u)*3 + m-1]; }
        else             { a = x1_2[(z0*64 + u)*5 + m-4];  b = x1_2[((z0+1)*64 + u)*5 + m-4]; }
        x1s[rec*XSTR + m] = pk(a, b);
    }

    // thread identities
    // Phase A: rec = tid & 31 -> (zpA = rec&3, vlA = rec>>2), grp = tid>>5
    const int recA = tid & 31;
    const int grp  = tid >> 5;
    // Phase B: zp = tid&3, wo = (tid>>2)&15 (w = 4*wo..), vg = tid>>6 (v half)
    const int zp = tid & 3;
    const int wo = (tid >> 2) & 15;
    const int vg = tid >> 6;

    ull acc[4][9];
#pragma unroll
    for (int j = 0; j < 4; j++)
#pragma unroll
        for (int k = 0; k < 9; k++) acc[j][k] = 0ull;

    for (int vc = 0; vc < NVC; vc++) {
        // ---- stage x2s chunk [vl*4+zp][10] ----
        for (int idx = tid; idx < VT*ZP*9; idx += 128) {
            int rec = idx / 9; int n = idx % 9;
            int vl = rec >> 2, zpp = rec & 3;
            int v  = vc*VT + vl;
            int z0 = zbase + zpp*2;
            float a, b;
            if (n == 0)      { a = x2_0[z0*64 + v];            b = x2_0[(z0+1)*64 + v]; }
            else if (n < 4)  { a = x2_1[(z0*64 + v)*3 + n-1];  b = x2_1[((z0+1)*64 + v)*3 + n-1]; }
            else             { a = x2_2[(z0*64 + v)*5 + n-4];  b = x2_2[((z0+1)*64 + v)*5 + n-4]; }
            x2s[rec*XSTR + n] = pk(a, b);
        }
        __syncthreads();

        for (int ul = 0; ul < UT; ul++) {
            const int u = ubase + ul;
            // ---- kick off W tile copy (8v x 11p x 64w floats = 22.5KB) ----
            {
                const float* gsrc = g_Wt + (size_t)((u << 6) + vc*VT) * (NP*64);
#pragma unroll
                for (int i = 0; i < 11; i++) {
                    int c = tid + i*128;
                    cpasync16(wdst0 + c*16, gsrc + c*4);
                }
                cpcommit();
            }
            // -------- Phase A (4 path groups, per-group operand loads) --------
            {
                const ull* ap = x1s + (ul*ZP + (recA & 3))*XSTR;
                const ull* bp = x2s + recA*XSTR;
                ull* trec = t2s + recA*TREC;
                ull a[9], b[9];
                if (grp == 0) {
                    // p10 (2,2,2): a4-8, b4-8
                    LDP(a, ap, 4); LDP(a, ap, 6); a[8] = ap[8];
                    LDP(b, bp, 4); LDP(b, bp, 6); b[8] = bp[8];
                    pathA<10>(a, b, c2s, trec);
                } else if (grp == 1) {
                    // p5 (1,1,2): a1-3,b1-3 ; p8 (2,1,1): a4-8,b1-3
                    LDP(a, ap, 0); LDP(a, ap, 2); LDP(a, ap, 4); LDP(a, ap, 6); a[8] = ap[8];
                    LDP(b, bp, 0); LDP(b, bp, 2);
                    pathA<5>(a, b, c2s, trec);
                    pathA<8>(a, b, c2s, trec);
                } else if (grp == 2) {
                    // p6 (1,2,1), p2 (0,2,2), p4 (1,1,0), p3 (1,0,1): a0-3, b0-8
                    LDP(a, ap, 0); LDP(a, ap, 2);
                    LDP(b, bp, 0); LDP(b, bp, 2); LDP(b, bp, 4); LDP(b, bp, 6); b[8] = bp[8];
                    pathA<6>(a, b, c2s, trec);
                    pathA<2>(a, b, c2s, trec);
                    pathA<4>(a, b, c2s, trec);
                    pathA<3>(a, b, c2s, trec);
                } else {
                    // p7 (2,0,2), p9 (2,2,0), p1 (0,1,1), p0 (0,0,0): a0,a4-8, b0-8
                    a[0] = ap[0];
                    LDP(a, ap, 4); LDP(a, ap, 6); a[8] = ap[8];
                    LDP(b, bp, 0); LDP(b, bp, 2); LDP(b, bp, 4); LDP(b, bp, 6); b[8] = bp[8];
                    pathA<7>(a, b, c2s, trec);
                    pathA<9>(a, b, c2s, trec);
                    pathA<1>(a, b, c2s, trec);
                    pathA<0>(a, b, c2s, trec);
                }
            }
            cpwait0();
            __syncthreads();
            // -------- Phase B (vg half of v, 4 w, 1 z-pair per thread) --------
            {
                const float* wv = wsm + (vg*4) * (NP*64) + wo*4;
                const ull*   tp = t2s + ((vg*4)*ZP + zp)*TREC;
#pragma unroll 1
                for (int vi = 0; vi < 4; vi++) {
                    pathB<0>(wv, tp, acc);
                    pathB<1>(wv, tp, acc);
                    pathB<2>(wv, tp, acc);
                    pathB<3>(wv, tp, acc);
                    pathB<4>(wv, tp, acc);
                    pathB<5>(wv, tp, acc);
                    pathB<6>(wv, tp, acc);
                    pathB<7>(wv, tp, acc);
                    pathB<8>(wv, tp, acc);
                    pathB<9>(wv, tp, acc);
                    pathB<10>(wv, tp, acc);
                    wv += NP*64;        // next v in W tile
                    tp += ZP*TREC;      // next vl record
                }
            }
            __syncthreads();
        }
    }

    // ---- epilogue: combine u-splits & v-halves via atomics ----
    const int z0 = zbase + zp*2;
#pragma unroll
    for (int j = 0; j < 4; j++) {
        const int w = wo*4 + j;
#pragma unroll
        for (int k = 0; k < 9; k++) {
            float lo, hi;
            unpk(acc[j][k], lo, hi);
            atomicAdd(&out[(z0*64 + w)*9 + k], lo);
            atomicAdd(&out[((z0+1)*64 + w)*9 + k], hi);
        }
    }
}

// ---------------------------------------------------------------------------
extern "C" void kernel_launch(void* const* d_in, const int* in_sizes, int n_in,
                              void* d_out, int out_size) {
    const float* x1_0 = (const float*)d_in[0];
    const float* x2_0 = (const float*)d_in[1];
    const float* x1_1 = (const float*)d_in[2];
    const float* x2_1 = (const float*)d_in[3];
    const float* x1_2 = (const float*)d_in[4];
    const float* x2_2 = (const float*)d_in[5];
    const float* W    = (const float*)d_in[6];
    float* out = (float*)d_out;
    (void)in_sizes; (void)n_in;

    cudaFuncSetAttribute(tp_kernel, cudaFuncAttributeMaxDynamicSharedMemorySize, SMEM_BYTES);

    cudaMemsetAsync(d_out, 0, (size_t)out_size * sizeof(float), 0);

    int nW = 64 * 64 * NP * 64;
    transpose_W_kernel<<<nW / 256, 256>>>(W);

    dim3 grid(1024 / ZT, 64 / UT);   // (128, 8) = 1024 blocks
    tp_kernel<<<grid, 128, SMEM_BYTES>>>(
        x1_0, x2_0, x1_1, x2_1, x1_2, x2_2,
        (const float*)d_in[7],  (const float*)d_in[8],  (const float*)d_in[9],
        (const float*)d_in[10], (const float*)d_in[11], (const float*)d_in[12],
        (const float*)d_in[13], (const float*)d_in[14], (const float*)d_in[15],
        (const float*)d_in[16], (const float*)d_in[17],
        out);
}

// round 12
// speedup vs baseline: 1.2044x; 1.1997x over previous
#include <cuda_runtime.h>
#include <stdint.h>

// ---------------------------------------------------------------------------
// HarmonicFullyConnectedTensorProduct (lmax=2, MUL=64, BATCH=1024, 11 paths)
// v6: crossbar-byte-optimized.
//  - Phase B k-split: thread = (zp, 8w, kg in {l3=2, l3<=1}, v-half).
//    kg0: acc[8][5] over paths {2,5,7,10}; kg1: acc[8][4] over the rest.
//  - t records stored tight (no dup pads): pairs + single per path block.
//  - C staged as scalar floats, dup'd in-register (ALU) not via 2x smem bytes.
//  - W tile via cp.async (unchanged), 4 CTAs/SM.
// ---------------------------------------------------------------------------

typedef unsigned long long ull;

#define NP 11
__host__ __device__ constexpr int PL1[NP]  = {0,0,0,1,1,1,1,2,2,2,2};
__host__ __device__ constexpr int PL2[NP]  = {0,1,2,0,1,1,2,0,1,2,2};
__host__ __device__ constexpr int PL3[NP]  = {0,1,2,1,0,2,1,2,1,0,2};
__host__ __device__ constexpr int XOFF[3]  = {0,1,4};
// t-record path block offsets (blocks sized m3+(m3&1), 16B aligned), stride 46
__host__ __device__ constexpr int TOP[NP]  = {0,2,6,12,16,18,24,28,34,38,40};
// C float layout: per (m,n) slot = m3+(m3&1) floats; path bases (float units)
__host__ __device__ constexpr int CPB[NP]  = {0,2,14,44,56,74,128,188,218,278,328};
#define C_TOT 478

#define ZT 8          // z rows per CTA (4 z-pairs)
#define ZP 4          // z-pairs per CTA
#define UT 8
#define VT 8
#define NVC 8
#define TREC 46
#define XSTR 10

// smem layout (ull units)
#define X1_OFF 0                    // 32 rec * 10 = 320
#define X2_OFF 320                  // 32 rec * 10 = 320
#define C_OFF  640                  // 240 ull = 480 floats (478 used)
#define T_OFF  880                  // 32 rec * 46 = 1472
#define W_OFF  2352                 // 2816 ull = 5632 floats
#define SMEM_ULL  5168
#define SMEM_BYTES (SMEM_ULL*8)     // 41344 -> 4 CTAs/SM

// W transposed: [u][v][p][w] floats
__device__ float g_Wt[64 * 64 * NP * 64];

// ---------------- packed f32x2 helpers ----------------
__device__ __forceinline__ ull pk(float lo, float hi) {
    ull r;
    asm("mov.b64 %0, {%1, %2};" : "=l"(r) : "r"(__float_as_uint(lo)), "r"(__float_as_uint(hi)));
    return r;
}
__device__ __forceinline__ void unpk(ull v, float& lo, float& hi) {
    unsigned a, b;
    asm("mov.b64 {%0, %1}, %2;" : "=r"(a), "=r"(b) : "l"(v));
    lo = __uint_as_float(a); hi = __uint_as_float(b);
}
__device__ __forceinline__ ull fma2(ull a, ull b, ull c) {
    ull d;
    asm("fma.rn.f32x2 %0, %1, %2, %3;" : "=l"(d) : "l"(a), "l"(b), "l"(c));
    return d;
}
__device__ __forceinline__ ull mul2(ull a, ull b) {
    ull d;
    asm("mul.rn.f32x2 %0, %1, %2;" : "=l"(d) : "l"(a), "l"(b));
    return d;
}
__device__ __forceinline__ uint32_t s2u32(const void* p) {
    uint32_t a;
    asm("{ .reg .u64 t; cvta.to.shared.u64 t, %1; cvt.u32.u64 %0, t; }" : "=r"(a) : "l"(p));
    return a;
}
__device__ __forceinline__ void cpasync16(uint32_t dst, const void* src) {
    asm volatile("cp.async.cg.shared.global [%0], [%1], 16;" :: "r"(dst), "l"(src));
}
__device__ __forceinline__ void cpcommit() {
    asm volatile("cp.async.commit_group;");
}
__device__ __forceinline__ void cpwait0() {
    asm volatile("cp.async.wait_group 0;" ::: "memory");
}

// operand pair load from smem record (16B)
#define LDP(dst, src, i) { ulonglong2 _q = *(const ulonglong2*)((src) + (i)); \
                           (dst)[i] = _q.x; (dst)[(i)+1] = _q.y; }

// ---------------- W transpose ----------------
__global__ void transpose_W_kernel(const float* __restrict__ W) {
    int idx = blockIdx.x * 256 + threadIdx.x;   // g_Wt index, w fastest
    int w  = idx & 63;
    int p  = (idx >> 6) % NP;
    int uv = idx / (NP * 64);
    g_Wt[idx] = W[(((p << 6) + w) << 12) + uv];
}

// ---------------- Phase A: one path (scalar C from smem, dup in reg) --------
template <int P>
__device__ __forceinline__ void pathA(const ull* a, const ull* b,
                                      const float* __restrict__ cf, ull* trec) {
    constexpr int L1 = PL1[P], L2 = PL2[P], L3 = PL3[P];
    constexpr int M1 = 2*L1+1, M2 = 2*L2+1, M3 = 2*L3+1;
    constexpr int O1 = XOFF[L1], O2 = XOFF[L2];
    constexpr int CB = CPB[P], SLOT = M3 + (M3 & 1), TO = TOP[P];
    ull t[M3];
#pragma unroll
    for (int k = 0; k < M3; k++) t[k] = 0ull;
#pragma unroll
    for (int m = 0; m < M1; m++) {
        ull am = a[O1 + m];
#pragma unroll
        for (int n = 0; n < M2; n++) {
            ull o = mul2(am, b[O2 + n]);
            const float* cc = cf + CB + (m*M2 + n)*SLOT;
#pragma unroll
            for (int kk = 0; kk < M3/2; kk++) {
                float2 c2v = *(const float2*)(cc + 2*kk);
                t[2*kk]   = fma2(o, pk(c2v.x, c2v.x), t[2*kk]);
                t[2*kk+1] = fma2(o, pk(c2v.y, c2v.y), t[2*kk+1]);
            }
            // M3 is odd (1,3,5)
            float cl = cc[M3-1];
            t[M3-1] = fma2(o, pk(cl, cl), t[M3-1]);
        }
    }
#pragma unroll
    for (int kk = 0; kk < M3/2; kk++) {
        ulonglong2 s; s.x = t[2*kk]; s.y = t[2*kk+1];
        *(ulonglong2*)(trec + TO + 2*kk) = s;
    }
    trec[TO + M3 - 1] = t[M3 - 1];
}

// ---------------- Phase B path kernels: 8 w per thread ----------------------
template <int P>
__device__ __forceinline__ void pathB5(const float* __restrict__ wv,
                                       const ull* __restrict__ tp,
                                       ull (&acc)[8][5]) {
    constexpr int TO = TOP[P];
    float4 wa = *(const float4*)(wv + P*64);
    float4 wb = *(const float4*)(wv + P*64 + 4);
    ull wd[8];
    wd[0] = pk(wa.x, wa.x); wd[1] = pk(wa.y, wa.y);
    wd[2] = pk(wa.z, wa.z); wd[3] = pk(wa.w, wa.w);
    wd[4] = pk(wb.x, wb.x); wd[5] = pk(wb.y, wb.y);
    wd[6] = pk(wb.z, wb.z); wd[7] = pk(wb.w, wb.w);
    const ulonglong2* tc = (const ulonglong2*)(tp + TO);
    ulonglong2 q0 = tc[0], q1 = tc[1];
    ull t4 = tp[TO + 4];
    ull tv[5] = {q0.x, q0.y, q1.x, q1.y, t4};
#pragma unroll
    for (int j = 0; j < 8; j++)
#pragma unroll
        for (int k = 0; k < 5; k++)
            acc[j][k] = fma2(wd[j], tv[k], acc[j][k]);
}

template <int P>
__device__ __forceinline__ void pathB3(const float* __restrict__ wv,
                                       const ull* __restrict__ tp,
                                       ull (&acc)[8][5]) {
    constexpr int TO = TOP[P];
    float4 wa = *(const float4*)(wv + P*64);
    float4 wb = *(const float4*)(wv + P*64 + 4);
    ull wd[8];
    wd[0] = pk(wa.x, wa.x); wd[1] = pk(wa.y, wa.y);
    wd[2] = pk(wa.z, wa.z); wd[3] = pk(wa.w, wa.w);
    wd[4] = pk(wb.x, wb.x); wd[5] = pk(wb.y, wb.y);
    wd[6] = pk(wb.z, wb.z); wd[7] = pk(wb.w, wb.w);
    ulonglong2 q0 = *(const ulonglong2*)(tp + TO);
    ull t2 = tp[TO + 2];
    ull tv[3] = {q0.x, q0.y, t2};
#pragma unroll
    for (int j = 0; j < 8; j++)
#pragma unroll
        for (int k = 0; k < 3; k++)
            acc[j][1 + k] = fma2(wd[j], tv[k], acc[j][1 + k]);
}

template <int P>
__device__ __forceinline__ void pathB1(const float* __restrict__ wv,
                                       const ull* __restrict__ tp,
                                       ull (&acc)[8][5]) {
    constexpr int TO = TOP[P];
    float4 wa = *(const float4*)(wv + P*64);
    float4 wb = *(const float4*)(wv + P*64 + 4);
    ull tv = tp[TO];
    acc[0][0] = fma2(pk(wa.x, wa.x), tv, acc[0][0]);
    acc[1][0] = fma2(pk(wa.y, wa.y), tv, acc[1][0]);
    acc[2][0] = fma2(pk(wa.z, wa.z), tv, acc[2][0]);
    acc[3][0] = fma2(pk(wa.w, wa.w), tv, acc[3][0]);
    acc[4][0] = fma2(pk(wb.x, wb.x), tv, acc[4][0]);
    acc[5][0] = fma2(pk(wb.y, wb.y), tv, acc[5][0]);
    acc[6][0] = fma2(pk(wb.z, wb.z), tv, acc[6][0]);
    acc[7][0] = fma2(pk(wb.w, wb.w), tv, acc[7][0]);
}

// ---------------- main fused kernel ----------------
__global__ void __launch_bounds__(128, 4)
tp_kernel(const float* __restrict__ x1_0, const float* __restrict__ x2_0,
          const float* __restrict__ x1_1, const float* __restrict__ x2_1,
          const float* __restrict__ x1_2, const float* __restrict__ x2_2,
          const float* __restrict__ C0,  const float* __restrict__ C1,
          const float* __restrict__ C2,  const float* __restrict__ C3,
          const float* __restrict__ C4,  const float* __restrict__ C5,
          const float* __restrict__ C6,  const float* __restrict__ C7,
          const float* __restrict__ C8,  const float* __restrict__ C9,
          const float* __restrict__ C10,
          float* __restrict__ out) {
    extern __shared__ ull sm[];
    ull*   x1s = sm + X1_OFF;
    ull*   x2s = sm + X2_OFF;
    float* c2f = (float*)(sm + C_OFF);
    ull*   t2s = sm + T_OFF;
    const float* wsm = (const float*)(sm + W_OFF);
    const uint32_t wdst0 = s2u32(sm + W_OFF);

    const int tid   = threadIdx.x;
    const int zbase = blockIdx.x * ZT;
    const int ubase = blockIdx.y * UT;

    // ---- stage C as scalar floats ----
    {
        const float* cps[NP] = {C0,C1,C2,C3,C4,C5,C6,C7,C8,C9,C10};
        for (int idx = tid; idx < C_TOT; idx += 128) {
            int p = 0;
#pragma unroll
            for (int q = 1; q < NP; q++) if (idx >= CPB[q]) p = q;
            int off  = idx - CPB[p];
            int m3   = 2*PL3[p] + 1;
            int slot = m3 + (m3 & 1);
            int mn   = off / slot;
            int k    = off % slot;
            c2f[idx] = (k < m3) ? cps[p][mn*m3 + k] : 0.0f;
        }
    }
    // ---- stage x1s [ul*4+zp][10] ----
    for (int idx = tid; idx < UT*ZP*9; idx += 128) {
        int rec = idx / 9; int m = idx % 9;
        int ul = rec >> 2, zpp = rec & 3;
        int u  = ubase + ul;
        int z0 = zbase + zpp*2;
        float a, b;
        if (m == 0)      { a = x1_0[z0*64 + u];            b = x1_0[(z0+1)*64 + u]; }
        else if (m < 4)  { a = x1_1[(z0*64 + u)*3 + m-1];  b = x1_1[((z0+1)*64 + u)*3 + m-1]; }
        else             { a = x1_2[(z0*64 + u)*5 + m-4];  b = x1_2[((z0+1)*64 + u)*5 + m-4]; }
        x1s[rec*XSTR + m] = pk(a, b);
    }

    // thread identities
    const int recA = tid & 31;          // Phase A record (zp = recA&3, vl = recA>>2)
    const int grp  = tid >> 5;          // Phase A path group (0..3)
    const int zp   = tid & 3;           // both phases
    const int wo   = (tid >> 2) & 7;    // Phase B w-octet -> w = 8*wo..8*wo+7
    const int kg   = (tid >> 5) & 1;    // Phase B k-group: 0 -> l3=2, 1 -> l3<=1
    const int vg   = tid >> 6;          // Phase B v-half

    ull acc[8][5];
#pragma unroll
    for (int j = 0; j < 8; j++)
#pragma unroll
        for (int k = 0; k < 5; k++) acc[j][k] = 0ull;

    for (int vc = 0; vc < NVC; vc++) {
        // ---- stage x2s chunk [vl*4+zp][10] ----
        for (int idx = tid; idx < VT*ZP*9; idx += 128) {
            int rec = idx / 9; int n = idx % 9;
            int vl = rec >> 2, zpp = rec & 3;
            int v  = vc*VT + vl;
            int z0 = zbase + zpp*2;
            float a, b;
            if (n == 0)      { a = x2_0[z0*64 + v];            b = x2_0[(z0+1)*64 + v]; }
            else if (n < 4)  { a = x2_1[(z0*64 + v)*3 + n-1];  b = x2_1[((z0+1)*64 + v)*3 + n-1]; }
            else             { a = x2_2[(z0*64 + v)*5 + n-4];  b = x2_2[((z0+1)*64 + v)*5 + n-4]; }
            x2s[rec*XSTR + n] = pk(a, b);
        }
        __syncthreads();

        for (int ul = 0; ul < UT; ul++) {
            const int u = ubase + ul;
            // ---- kick off W tile copy (8v x 11p x 64w floats = 22.5KB) ----
            {
                const float* gsrc = g_Wt + (size_t)((u << 6) + vc*VT) * (NP*64);
#pragma unroll
                for (int i = 0; i < 11; i++) {
                    int c = tid + i*128;
                    cpasync16(wdst0 + c*16, gsrc + c*4);
                }
                cpcommit();
            }
            // -------- Phase A (4 path groups, scoped operand loads) --------
            {
                const ull* ap = x1s + (ul*ZP + (recA & 3))*XSTR;
                const ull* bp = x2s + recA*XSTR;
                ull* trec = t2s + recA*TREC;
                if (grp == 0) {            // {p10}
                    ull a[9], b[9];
                    LDP(a, ap, 4); LDP(a, ap, 6); a[8] = ap[8];
                    LDP(b, bp, 4); LDP(b, bp, 6); b[8] = bp[8];
                    pathA<10>(a, b, c2f, trec);
                } else if (grp == 1) {     // {p2, p6, p3}
                    ull a[9], b[9];
                    LDP(a, ap, 0); LDP(a, ap, 2);
                    LDP(b, bp, 4); LDP(b, bp, 6); b[8] = bp[8];
                    pathA<2>(a, b, c2f, trec);
                    pathA<6>(a, b, c2f, trec);
                    b[0] = bp[0];
                    pathA<3>(a, b, c2f, trec);
                } else if (grp == 2) {     // {p5, p8}
                    ull a[9], b[9];
                    LDP(a, ap, 0); LDP(a, ap, 2);
                    LDP(b, bp, 0); LDP(b, bp, 2);
                    pathA<5>(a, b, c2f, trec);
                    LDP(a, ap, 4); LDP(a, ap, 6); a[8] = ap[8];
                    pathA<8>(a, b, c2f, trec);
                } else {                   // {p7, p9, p0, p1, p4}
                    ull a[9], b[9];
                    LDP(a, ap, 4); LDP(a, ap, 6); a[8] = ap[8];
                    b[0] = bp[0];
                    pathA<7>(a, b, c2f, trec);
                    LDP(b, bp, 4); LDP(b, bp, 6); b[8] = bp[8];
                    pathA<9>(a, b, c2f, trec);
                    a[0] = ap[0];
                    LDP(b, bp, 0); LDP(b, bp, 2);
                    pathA<0>(a, b, c2f, trec);
                    pathA<1>(a, b, c2f, trec);
                    LDP(a, ap, 0); LDP(a, ap, 2);
                    pathA<4>(a, b, c2f, trec);
                }
            }
            cpwait0();
            __syncthreads();
            // -------- Phase B: 8 w, k-split, v-half --------
            if (kg == 0) {
                const float* wv = wsm + (vg*4)*(NP*64) + wo*8;
                const ull*   tp = t2s + ((vg*4)*ZP + zp)*TREC;
#pragma unroll 1
                for (int vi = 0; vi < 4; vi++) {
                    pathB5<2>(wv, tp, acc);
                    pathB5<5>(wv, tp, acc);
                    pathB5<7>(wv, tp, acc);
                    pathB5<10>(wv, tp, acc);
                    wv += NP*64;
                    tp += ZP*TREC;
                }
            } else {
                const float* wv = wsm + (vg*4)*(NP*64) + wo*8;
                const ull*   tp = t2s + ((vg*4)*ZP + zp)*TREC;
#pragma unroll 1
                for (int vi = 0; vi < 4; vi++) {
                    pathB3<1>(wv, tp, acc);
                    pathB3<3>(wv, tp, acc);
                    pathB3<6>(wv, tp, acc);
                    pathB3<8>(wv, tp, acc);
                    pathB1<0>(wv, tp, acc);
                    pathB1<4>(wv, tp, acc);
                    pathB1<9>(wv, tp, acc);
                    wv += NP*64;
                    tp += ZP*TREC;
                }
            }
            __syncthreads();
        }
    }

    // ---- epilogue: combine u-splits & v-halves via atomics ----
    const int z0 = zbase + zp*2;
    if (kg == 0) {
#pragma unroll
        for (int j = 0; j < 8; j++) {
            const int w = wo*8 + j;
#pragma unroll
            for (int k = 0; k < 5; k++) {
                float lo, hi;
                unpk(acc[j][k], lo, hi);
                atomicAdd(&out[(z0*64 + w)*9 + 4 + k], lo);
                atomicAdd(&out[((z0+1)*64 + w)*9 + 4 + k], hi);
            }
        }
    } else {
#pragma unroll
        for (int j = 0; j < 8; j++) {
            const int w = wo*8 + j;
#pragma unroll
            for (int k = 0; k < 4; k++) {
                float lo, hi;
                unpk(acc[j][k], lo, hi);
                atomicAdd(&out[(z0*64 + w)*9 + k], lo);
                atomicAdd(&out[((z0+1)*64 + w)*9 + k], hi);
            }
        }
    }
}

// ---------------------------------------------------------------------------
extern "C" void kernel_launch(void* const* d_in, const int* in_sizes, int n_in,
                              void* d_out, int out_size) {
    const float* x1_0 = (const float*)d_in[0];
    const float* x2_0 = (const float*)d_in[1];
    const float* x1_1 = (const float*)d_in[2];
    const float* x2_1 = (const float*)d_in[3];
    const float* x1_2 = (const float*)d_in[4];
    const float* x2_2 = (const float*)d_in[5];
    const float* W    = (const float*)d_in[6];
    float* out = (float*)d_out;
    (void)in_sizes; (void)n_in;

    cudaFuncSetAttribute(tp_kernel, cudaFuncAttributeMaxDynamicSharedMemorySize, SMEM_BYTES);

    cudaMemsetAsync(d_out, 0, (size_t)out_size * sizeof(float), 0);

    int nW = 64 * 64 * NP * 64;
    transpose_W_kernel<<<nW / 256, 256>>>(W);

    dim3 grid(1024 / ZT, 64 / UT);   // (128, 8) = 1024 blocks
    tp_kernel<<<grid, 128, SMEM_BYTES>>>(
        x1_0, x2_0, x1_1, x2_1, x1_2, x2_2,
        (const float*)d_in[7],  (const float*)d_in[8],  (const float*)d_in[9],
        (const float*)d_in[10], (const float*)d_in[11], (const float*)d_in[12],
        (const float*)d_in[13], (const float*)d_in[14], (const float*)d_in[15],
        (const float*)d_in[16], (const float*)d_in[17],
        out);
}

// round 13
// speedup vs baseline: 1.2055x; 1.0009x over previous
#include <cuda_runtime.h>
#include <stdint.h>

// ---------------------------------------------------------------------------
// HarmonicFullyConnectedTensorProduct (lmax=2, MUL=64, BATCH=1024, 11 paths)
// v6: crossbar-byte-optimized.
//  - Phase B k-split: thread = (zp, 8w, kg in {l3=2, l3<=1}, v-half).
//    kg0: acc[8][5] over paths {2,5,7,10}; kg1: acc[8][4] over the rest.
//  - t records stored tight (no dup pads): pairs + single per path block.
//  - C staged as scalar floats, dup'd in-register (ALU) not via 2x smem bytes.
//  - W tile via cp.async (unchanged), 4 CTAs/SM.
// ---------------------------------------------------------------------------

typedef unsigned long long ull;

#define NP 11
__host__ __device__ constexpr int PL1[NP]  = {0,0,0,1,1,1,1,2,2,2,2};
__host__ __device__ constexpr int PL2[NP]  = {0,1,2,0,1,1,2,0,1,2,2};
__host__ __device__ constexpr int PL3[NP]  = {0,1,2,1,0,2,1,2,1,0,2};
__host__ __device__ constexpr int XOFF[3]  = {0,1,4};
// t-record path block offsets (blocks sized m3+(m3&1), 16B aligned), stride 46
__host__ __device__ constexpr int TOP[NP]  = {0,2,6,12,16,18,24,28,34,38,40};
// C float layout: per (m,n) slot = m3+(m3&1) floats; path bases (float units)
__host__ __device__ constexpr int CPB[NP]  = {0,2,14,44,56,74,128,188,218,278,328};
#define C_TOT 478

#define ZT 8          // z rows per CTA (4 z-pairs)
#define ZP 4          // z-pairs per CTA
#define UT 8
#define VT 8
#define NVC 8
#define TREC 46
#define XSTR 10

// smem layout (ull units)
#define X1_OFF 0                    // 32 rec * 10 = 320
#define X2_OFF 320                  // 32 rec * 10 = 320
#define C_OFF  640                  // 240 ull = 480 floats (478 used)
#define T_OFF  880                  // 32 rec * 46 = 1472
#define W_OFF  2352                 // 2816 ull = 5632 floats
#define SMEM_ULL  5168
#define SMEM_BYTES (SMEM_ULL*8)     // 41344 -> 4 CTAs/SM

// W transposed: [u][v][p][w] floats
__device__ float g_Wt[64 * 64 * NP * 64];

// ---------------- packed f32x2 helpers ----------------
__device__ __forceinline__ ull pk(float lo, float hi) {
    ull r;
    asm("mov.b64 %0, {%1, %2};" : "=l"(r) : "r"(__float_as_uint(lo)), "r"(__float_as_uint(hi)));
    return r;
}
__device__ __forceinline__ void unpk(ull v, float& lo, float& hi) {
    unsigned a, b;
    asm("mov.b64 {%0, %1}, %2;" : "=r"(a), "=r"(b) : "l"(v));
    lo = __uint_as_float(a); hi = __uint_as_float(b);
}
__device__ __forceinline__ ull fma2(ull a, ull b, ull c) {
    ull d;
    asm("fma.rn.f32x2 %0, %1, %2, %3;" : "=l"(d) : "l"(a), "l"(b), "l"(c));
    return d;
}
__device__ __forceinline__ ull mul2(ull a, ull b) {
    ull d;
    asm("mul.rn.f32x2 %0, %1, %2;" : "=l"(d) : "l"(a), "l"(b));
    return d;
}
__device__ __forceinline__ uint32_t s2u32(const void* p) {
    uint32_t a;
    asm("{ .reg .u64 t; cvta.to.shared.u64 t, %1; cvt.u32.u64 %0, t; }" : "=r"(a) : "l"(p));
    return a;
}
__device__ __forceinline__ void cpasync16(uint32_t dst, const void* src) {
    asm volatile("cp.async.cg.shared.global [%0], [%1], 16;" :: "r"(dst), "l"(src));
}
__device__ __forceinline__ void cpcommit() {
    asm volatile("cp.async.commit_group;");
}
__device__ __forceinline__ void cpwait0() {
    asm volatile("cp.async.wait_group 0;" ::: "memory");
}

// operand pair load from smem record (16B)
#define LDP(dst, src, i) { ulonglong2 _q = *(const ulonglong2*)((src) + (i)); \
                           (dst)[i] = _q.x; (dst)[(i)+1] = _q.y; }

// ---------------- W transpose ----------------
__global__ void transpose_W_kernel(const float* __restrict__ W) {
    int idx = blockIdx.x * 256 + threadIdx.x;   // g_Wt index, w fastest
    int w  = idx & 63;
    int p  = (idx >> 6) % NP;
    int uv = idx / (NP * 64);
    g_Wt[idx] = W[(((p << 6) + w) << 12) + uv];
}

// ---------------- Phase A: one path (scalar C from smem, dup in reg) --------
template <int P>
__device__ __forceinline__ void pathA(const ull* a, const ull* b,
                                      const float* __restrict__ cf, ull* trec) {
    constexpr int L1 = PL1[P], L2 = PL2[P], L3 = PL3[P];
    constexpr int M1 = 2*L1+1, M2 = 2*L2+1, M3 = 2*L3+1;
    constexpr int O1 = XOFF[L1], O2 = XOFF[L2];
    constexpr int CB = CPB[P], SLOT = M3 + (M3 & 1), TO = TOP[P];
    ull t[M3];
#pragma unroll
    for (int k = 0; k < M3; k++) t[k] = 0ull;
#pragma unroll
    for (int m = 0; m < M1; m++) {
        ull am = a[O1 + m];
#pragma unroll
        for (int n = 0; n < M2; n++) {
            ull o = mul2(am, b[O2 + n]);
            const float* cc = cf + CB + (m*M2 + n)*SLOT;
#pragma unroll
            for (int kk = 0; kk < M3/2; kk++) {
                float2 c2v = *(const float2*)(cc + 2*kk);
                t[2*kk]   = fma2(o, pk(c2v.x, c2v.x), t[2*kk]);
                t[2*kk+1] = fma2(o, pk(c2v.y, c2v.y), t[2*kk+1]);
            }
            // M3 is odd (1,3,5)
            float cl = cc[M3-1];
            t[M3-1] = fma2(o, pk(cl, cl), t[M3-1]);
        }
    }
#pragma unroll
    for (int kk = 0; kk < M3/2; kk++) {
        ulonglong2 s; s.x = t[2*kk]; s.y = t[2*kk+1];
        *(ulonglong2*)(trec + TO + 2*kk) = s;
    }
    trec[TO + M3 - 1] = t[M3 - 1];
}

// ---------------- Phase B path kernels: 8 w per thread ----------------------
template <int P>
__device__ __forceinline__ void pathB5(const float* __restrict__ wv,
                                       const ull* __restrict__ tp,
                                       ull (&acc)[8][5]) {
    constexpr int TO = TOP[P];
    float4 wa = *(const float4*)(wv + P*64);
    float4 wb = *(const float4*)(wv + P*64 + 4);
    ull wd[8];
    wd[0] = pk(wa.x, wa.x); wd[1] = pk(wa.y, wa.y);
    wd[2] = pk(wa.z, wa.z); wd[3] = pk(wa.w, wa.w);
    wd[4] = pk(wb.x, wb.x); wd[5] = pk(wb.y, wb.y);
    wd[6] = pk(wb.z, wb.z); wd[7] = pk(wb.w, wb.w);
    const ulonglong2* tc = (const ulonglong2*)(tp + TO);
    ulonglong2 q0 = tc[0], q1 = tc[1];
    ull t4 = tp[TO + 4];
    ull tv[5] = {q0.x, q0.y, q1.x, q1.y, t4};
#pragma unroll
    for (int j = 0; j < 8; j++)
#pragma unroll
        for (int k = 0; k < 5; k++)
            acc[j][k] = fma2(wd[j], tv[k], acc[j][k]);
}

template <int P>
__device__ __forceinline__ void pathB3(const float* __restrict__ wv,
                                       const ull* __restrict__ tp,
                                       ull (&acc)[8][5]) {
    constexpr int TO = TOP[P];
    float4 wa = *(const float4*)(wv + P*64);
    float4 wb = *(const float4*)(wv + P*64 + 4);
    ull wd[8];
    wd[0] = pk(wa.x, wa.x); wd[1] = pk(wa.y, wa.y);
    wd[2] = pk(wa.z, wa.z); wd[3] = pk(wa.w, wa.w);
    wd[4] = pk(wb.x, wb.x); wd[5] = pk(wb.y, wb.y);
    wd[6] = pk(wb.z, wb.z); wd[7] = pk(wb.w, wb.w);
    ulonglong2 q0 = *(const ulonglong2*)(tp + TO);
    ull t2 = tp[TO + 2];
    ull tv[3] = {q0.x, q0.y, t2};
#pragma unroll
    for (int j = 0; j < 8; j++)
#pragma unroll
        for (int k = 0; k < 3; k++)
            acc[j][1 + k] = fma2(wd[j], tv[k], acc[j][1 + k]);
}

template <int P>
__device__ __forceinline__ void pathB1(const float* __restrict__ wv,
                                       const ull* __restrict__ tp,
                                       ull (&acc)[8][5]) {
    constexpr int TO = TOP[P];
    float4 wa = *(const float4*)(wv + P*64);
    float4 wb = *(const float4*)(wv + P*64 + 4);
    ull tv = tp[TO];
    acc[0][0] = fma2(pk(wa.x, wa.x), tv, acc[0][0]);
    acc[1][0] = fma2(pk(wa.y, wa.y), tv, acc[1][0]);
    acc[2][0] = fma2(pk(wa.z, wa.z), tv, acc[2][0]);
    acc[3][0] = fma2(pk(wa.w, wa.w), tv, acc[3][0]);
    acc[4][0] = fma2(pk(wb.x, wb.x), tv, acc[4][0]);
    acc[5][0] = fma2(pk(wb.y, wb.y), tv, acc[5][0]);
    acc[6][0] = fma2(pk(wb.z, wb.z), tv, acc[6][0]);
    acc[7][0] = fma2(pk(wb.w, wb.w), tv, acc[7][0]);
}

// ---------------- main fused kernel ----------------
__global__ void __launch_bounds__(128, 4)
tp_kernel(const float* __restrict__ x1_0, const float* __restrict__ x2_0,
          const float* __restrict__ x1_1, const float* __restrict__ x2_1,
          const float* __restrict__ x1_2, const float* __restrict__ x2_2,
          const float* __restrict__ C0,  const float* __restrict__ C1,
          const float* __restrict__ C2,  const float* __restrict__ C3,
          const float* __restrict__ C4,  const float* __restrict__ C5,
          const float* __restrict__ C6,  const float* __restrict__ C7,
          const float* __restrict__ C8,  const float* __restrict__ C9,
          const float* __restrict__ C10,
          float* __restrict__ out) {
    extern __shared__ ull sm[];
    ull*   x1s = sm + X1_OFF;
    ull*   x2s = sm + X2_OFF;
    float* c2f = (float*)(sm + C_OFF);
    ull*   t2s = sm + T_OFF;
    const float* wsm = (const float*)(sm + W_OFF);
    const uint32_t wdst0 = s2u32(sm + W_OFF);

    const int tid   = threadIdx.x;
    const int zbase = blockIdx.x * ZT;
    const int ubase = blockIdx.y * UT;

    // ---- stage C as scalar floats ----
    {
        const float* cps[NP] = {C0,C1,C2,C3,C4,C5,C6,C7,C8,C9,C10};
        for (int idx = tid; idx < C_TOT; idx += 128) {
            int p = 0;
#pragma unroll
            for (int q = 1; q < NP; q++) if (idx >= CPB[q]) p = q;
            int off  = idx - CPB[p];
            int m3   = 2*PL3[p] + 1;
            int slot = m3 + (m3 & 1);
            int mn   = off / slot;
            int k    = off % slot;
            c2f[idx] = (k < m3) ? cps[p][mn*m3 + k] : 0.0f;
        }
    }
    // ---- stage x1s [ul*4+zp][10] ----
    for (int idx = tid; idx < UT*ZP*9; idx += 128) {
        int rec = idx / 9; int m = idx % 9;
        int ul = rec >> 2, zpp = rec & 3;
        int u  = ubase + ul;
        int z0 = zbase + zpp*2;
        float a, b;
        if (m == 0)      { a = x1_0[z0*64 + u];            b = x1_0[(z0+1)*64 + u]; }
        else if (m < 4)  { a = x1_1[(z0*64 + u)*3 + m-1];  b = x1_1[((z0+1)*64 + u)*3 + m-1]; }
        else             { a = x1_2[(z0*64 + u)*5 + m-4];  b = x1_2[((z0+1)*64 + u)*5 + m-4]; }
        x1s[rec*XSTR + m] = pk(a, b);
    }

    // thread identities
    const int recA = tid & 31;          // Phase A record (zp = recA&3, vl = recA>>2)
    const int grp  = tid >> 5;          // Phase A path group (0..3)
    const int zp   = tid & 3;           // both phases
    const int wo   = (tid >> 2) & 7;    // Phase B w-octet -> w = 8*wo..8*wo+7
    const int kg   = (tid >> 5) & 1;    // Phase B k-group: 0 -> l3=2, 1 -> l3<=1
    const int vg   = tid >> 6;          // Phase B v-half

    ull acc[8][5];
#pragma unroll
    for (int j = 0; j < 8; j++)
#pragma unroll
        for (int k = 0; k < 5; k++) acc[j][k] = 0ull;

    for (int vc = 0; vc < NVC; vc++) {
        // ---- stage x2s chunk [vl*4+zp][10] ----
        for (int idx = tid; idx < VT*ZP*9; idx += 128) {
            int rec = idx / 9; int n = idx % 9;
            int vl = rec >> 2, zpp = rec & 3;
            int v  = vc*VT + vl;
            int z0 = zbase + zpp*2;
            float a, b;
            if (n == 0)      { a = x2_0[z0*64 + v];            b = x2_0[(z0+1)*64 + v]; }
            else if (n < 4)  { a = x2_1[(z0*64 + v)*3 + n-1];  b = x2_1[((z0+1)*64 + v)*3 + n-1]; }
            else             { a = x2_2[(z0*64 + v)*5 + n-4];  b = x2_2[((z0+1)*64 + v)*5 + n-4]; }
            x2s[rec*XSTR + n] = pk(a, b);
        }
        __syncthreads();

        for (int ul = 0; ul < UT; ul++) {
            const int u = ubase + ul;
            // ---- kick off W tile copy (8v x 11p x 64w floats = 22.5KB) ----
            {
                const float* gsrc = g_Wt + (size_t)((u << 6) + vc*VT) * (NP*64);
#pragma unroll
                for (int i = 0; i < 11; i++) {
                    int c = tid + i*128;
                    cpasync16(wdst0 + c*16, gsrc + c*4);
                }
                cpcommit();
            }
            // -------- Phase A (4 path groups, scoped operand loads) --------
            {
                const ull* ap = x1s + (ul*ZP + (recA & 3))*XSTR;
                const ull* bp = x2s + recA*XSTR;
                ull* trec = t2s + recA*TREC;
                if (grp == 0) {            // {p10}
                    ull a[9], b[9];
                    LDP(a, ap, 4); LDP(a, ap, 6); a[8] = ap[8];
                    LDP(b, bp, 4); LDP(b, bp, 6); b[8] = bp[8];
                    pathA<10>(a, b, c2f, trec);
                } else if (grp == 1) {     // {p2, p6, p3}
                    ull a[9], b[9];
                    LDP(a, ap, 0); LDP(a, ap, 2);
                    LDP(b, bp, 4); LDP(b, bp, 6); b[8] = bp[8];
                    pathA<2>(a, b, c2f, trec);
                    pathA<6>(a, b, c2f, trec);
                    b[0] = bp[0];
                    pathA<3>(a, b, c2f, trec);
                } else if (grp == 2) {     // {p5, p8}
                    ull a[9], b[9];
                    LDP(a, ap, 0); LDP(a, ap, 2);
                    LDP(b, bp, 0); LDP(b, bp, 2);
                    pathA<5>(a, b, c2f, trec);
                    LDP(a, ap, 4); LDP(a, ap, 6); a[8] = ap[8];
                    pathA<8>(a, b, c2f, trec);
                } else {                   // {p7, p9, p0, p1, p4}
                    ull a[9], b[9];
                    LDP(a, ap, 4); LDP(a, ap, 6); a[8] = ap[8];
                    b[0] = bp[0];
                    pathA<7>(a, b, c2f, trec);
                    LDP(b, bp, 4); LDP(b, bp, 6); b[8] = bp[8];
                    pathA<9>(a, b, c2f, trec);
                    a[0] = ap[0];
                    LDP(b, bp, 0); LDP(b, bp, 2);
                    pathA<0>(a, b, c2f, trec);
                    pathA<1>(a, b, c2f, trec);
                    LDP(a, ap, 0); LDP(a, ap, 2);
                    pathA<4>(a, b, c2f, trec);
                }
            }
            cpwait0();
            __syncthreads();
            // -------- Phase B: 8 w, k-split, v-half --------
            if (kg == 0) {
                const float* wv = wsm + (vg*4)*(NP*64) + wo*8;
                const ull*   tp = t2s + ((vg*4)*ZP + zp)*TREC;
#pragma unroll 1
                for (int vi = 0; vi < 4; vi++) {
                    pathB5<2>(wv, tp, acc);
                    pathB5<5>(wv, tp, acc);
                    pathB5<7>(wv, tp, acc);
                    pathB5<10>(wv, tp, acc);
                    wv += NP*64;
                    tp += ZP*TREC;
                }
            } else {
                const float* wv = wsm + (vg*4)*(NP*64) + wo*8;
                const ull*   tp = t2s + ((vg*4)*ZP + zp)*TREC;
#pragma unroll 1
                for (int vi = 0; vi < 4; vi++) {
                    pathB3<1>(wv, tp, acc);
                    pathB3<3>(wv, tp, acc);
                    pathB3<6>(wv, tp, acc);
                    pathB3<8>(wv, tp, acc);
                    pathB1<0>(wv, tp, acc);
                    pathB1<4>(wv, tp, acc);
                    pathB1<9>(wv, tp, acc);
                    wv += NP*64;
                    tp += ZP*TREC;
                }
            }
            __syncthreads();
        }
    }

    // ---- epilogue: combine u-splits & v-halves via atomics ----
    const int z0 = zbase + zp*2;
    if (kg == 0) {
#pragma unroll
        for (int j = 0; j < 8; j++) {
            const int w = wo*8 + j;
#pragma unroll
            for (int k = 0; k < 5; k++) {
                float lo, hi;
                unpk(acc[j][k], lo, hi);
                atomicAdd(&out[(z0*64 + w)*9 + 4 + k], lo);
                atomicAdd(&out[((z0+1)*64 + w)*9 + 4 + k], hi);
            }
        }
    } else {
#pragma unroll
        for (int j = 0; j < 8; j++) {
            const int w = wo*8 + j;
#pragma unroll
            for (int k = 0; k < 4; k++) {
                float lo, hi;
                unpk(acc[j][k], lo, hi);
                atomicAdd(&out[(z0*64 + w)*9 + k], lo);
                atomicAdd(&out[((z0+1)*64 + w)*9 + k], hi);
            }
        }
    }
}

// ---------------------------------------------------------------------------
extern "C" void kernel_launch(void* const* d_in, const int* in_sizes, int n_in,
                              void* d_out, int out_size) {
    const float* x1_0 = (const float*)d_in[0];
    const float* x2_0 = (const float*)d_in[1];
    const float* x1_1 = (const float*)d_in[2];
    const float* x2_1 = (const float*)d_in[3];
    const float* x1_2 = (const float*)d_in[4];
    const float* x2_2 = (const float*)d_in[5];
    const float* W    = (const float*)d_in[6];
    float* out = (float*)d_out;
    (void)in_sizes; (void)n_in;

    cudaFuncSetAttribute(tp_kernel, cudaFuncAttributeMaxDynamicSharedMemorySize, SMEM_BYTES);

    cudaMemsetAsync(d_out, 0, (size_t)out_size * sizeof(float), 0);

    int nW = 64 * 64 * NP * 64;
    transpose_W_kernel<<<nW / 256, 256>>>(W);

    dim3 grid(1024 / ZT, 64 / UT);   // (128, 8) = 1024 blocks
    tp_kernel<<<grid, 128, SMEM_BYTES>>>(
        x1_0, x2_0, x1_1, x2_1, x1_2, x2_2,
        (const float*)d_in[7],  (const float*)d_in[8],  (const float*)d_in[9],
        (const float*)d_in[10], (const float*)d_in[11], (const float*)d_in[12],
        (const float*)d_in[13], (const float*)d_in[14], (const float*)d_in[15],
        (const float*)d_in[16], (const float*)d_in[17],
        out);
}